// round 15
// baseline (speedup 1.0000x reference)
#include <cuda_runtime.h>
#include <cuda_fp16.h>
#include <cstdint>
#include <math.h>

#define Bq 4
#define Sq 2048
#define Dq 1024
#define Fq 4096
#define Mq (Bq*Sq)     // 8192
#define CH 32
#define CL (Sq/CH)     // 64
#define LDT 40         // smem row stride in halves (BK=32 + 8 pad)
#define STAGE_H (128*LDT)            // halves per tile (5120)
#define TILES_PER_STAGE 2            // A, B
#define STG_BYTES (TILES_PER_STAGE*STAGE_H*2)   // 20480
#define NSTAGE 4
#define SMEM_BYTES (NSTAGE*STG_BYTES)           // 81920
#define BLKS_PER_CHUNK 16            // (Bq*Dq)/256

// ---------------- scratch ----------------
__device__ __half g_xn[(size_t)Mq*Dq];
__device__ __half g_wqkvw[(size_t)4*Dq*Dq];   // [r rows | v rows | w/k interleaved]
__device__ __half g_wo[(size_t)Dq*Dq];
__device__ __half g_wrk[(size_t)(Dq+Fq)*Dq];  // [rec|key]
__device__ __half g_wval[(size_t)Dq*Fq];
__device__ __half g_r16[(size_t)Mq*Dq];
__device__ __half g_v16[(size_t)Mq*Dq];
__device__ __half g_e  [(size_t)Mq*Dq];       // exp(k - exp(w)), fp16
__device__ float  g_x1 [(size_t)Mq*Dq];
__device__ float  g_r2 [(size_t)Mq*Dq];
__device__ __half g_rw[(size_t)Mq*Dq];
__device__ __half g_k2[(size_t)Mq*Fq];
__device__ float  g_loc[(size_t)CH*Bq*2*Dq];
__device__ int    g_cnt[CH];                  // chunk-completion counters (reset by GEMM5)

// ---------------- helpers ----------------
__device__ __forceinline__ uint32_t packh(__half a, __half b) {
    __half2 p(a, b);
    return *reinterpret_cast<uint32_t*>(&p);
}
__device__ __forceinline__ uint2 cvt4(float4 v) {
    return make_uint2(packh(__float2half(v.x), __float2half(v.y)),
                      packh(__float2half(v.z), __float2half(v.w)));
}
__device__ __forceinline__ __half hsig(float x) {
    return __float2half(1.f / (1.f + expf(-x)));
}
__device__ __forceinline__ void ldsm4(uint32_t& r0, uint32_t& r1, uint32_t& r2, uint32_t& r3,
                                      uint32_t addr) {
    asm volatile("ldmatrix.sync.aligned.m8n8.x4.shared.b16 {%0,%1,%2,%3}, [%4];"
                 : "=r"(r0), "=r"(r1), "=r"(r2), "=r"(r3) : "r"(addr));
}

// ---------------- fused weight convert (with optional row interleave) ----------
struct CvtJob  { const float4* s; uint2* d; int n4; int kq; int rstride; };
struct CvtJobs { CvtJob j[8]; };
__global__ void cvtall_kernel(CvtJobs js)
{
    const CvtJob jb = js.j[blockIdx.y];
    const int i = blockIdx.x * blockDim.x + threadIdx.x;
    if (i >= jb.n4) return;
    const int row = i / jb.kq;
    const int col = i - row * jb.kq;
    jb.d[(size_t)row * jb.rstride * jb.kq + col] = cvt4(jb.s[i]);
}

// ---------------- layernorm -> fp16 ----------------
__global__ void ln_cvt_kernel(const float* __restrict__ x,
                              const float* __restrict__ gamma,
                              const float* __restrict__ beta,
                              uint2* __restrict__ oh)
{
    const int row = blockIdx.x;
    const float4* xr = reinterpret_cast<const float4*>(x) + (size_t)row * (Dq/4);
    float4 v = xr[threadIdx.x];
    float s  = v.x + v.y + v.z + v.w;
    float ss = v.x*v.x + v.y*v.y + v.z*v.z + v.w*v.w;
    #pragma unroll
    for (int o = 16; o > 0; o >>= 1) {
        s  += __shfl_xor_sync(0xffffffffu, s,  o);
        ss += __shfl_xor_sync(0xffffffffu, ss, o);
    }
    __shared__ float rs[8], rss[8];
    const int warp = threadIdx.x >> 5;
    if ((threadIdx.x & 31) == 0) { rs[warp] = s; rss[warp] = ss; }
    __syncthreads();
    float ts = 0.f, tss = 0.f;
    #pragma unroll
    for (int i = 0; i < 8; i++) { ts += rs[i]; tss += rss[i]; }
    const float mu   = ts * (1.0f/Dq);
    const float var  = tss * (1.0f/Dq) - mu*mu;
    const float rstd = rsqrtf(var + 1e-5f);
    const float4 g4 = reinterpret_cast<const float4*>(gamma)[threadIdx.x];
    const float4 b4 = reinterpret_cast<const float4*>(beta )[threadIdx.x];
    float4 o;
    o.x = (v.x - mu)*rstd*g4.x + b4.x;
    o.y = (v.y - mu)*rstd*g4.y + b4.y;
    o.z = (v.z - mu)*rstd*g4.z + b4.z;
    o.w = (v.w - mu)*rstd*g4.w + b4.w;
    oh[(size_t)row * (Dq/4) + threadIdx.x] = cvt4(o);
}

// ---------------- HMMA GEMM: BK=32, 4-stage ring, wait_group 2 ----------------
// ONE __syncthreads per kt. ldmatrix fragment loads.
// EPI: 3 = acc + R -> C;  4 = R + MUL(float)*acc -> C
//      5 = qkvw: x<8 sigmoid->Ch fp16; 8<=x<16 raw->Cv fp16; x>=16 (w,k) pairs ->
//          Ce = expf(k - expf(w)) fp16; CTA(0,0) also resets g_cnt.
//      6 = rec|key: x<8 sigmoid->C fp32 [M,1024]; else relu^2 -> Ch fp16 [M,4096]
template<int EPI>
__global__ void __launch_bounds__(256, 2)
mma_gemm(const __half* __restrict__ A, const __half* __restrict__ B,
         float* __restrict__ C, __half* __restrict__ Ch,
         __half* __restrict__ Cv, __half* __restrict__ Ce,
         const float* __restrict__ R, const float* __restrict__ MUL,
         int N, int K)
{
    extern __shared__ __half dyn[];

    const int tid = threadIdx.x;
    const int block_row = blockIdx.y * 128;
    const int block_col = blockIdx.x * 128;

    const uint32_t sbase = (uint32_t)__cvta_generic_to_shared(dyn);

    // loaders: 2 threads per row, each 2 x 16B per tile
    const int lr = tid >> 1;
    const int sg = (tid & 1) * 2;
    const __half* gA = A + (size_t)(block_row + lr) * K;
    const __half* gB = B + (size_t)(block_col + lr) * K;
    const uint32_t srow = sbase + (uint32_t)(lr * LDT) * 2;

    #define LOADSTAGE(st, ko)                                                          \
    do {                                                                               \
        const uint32_t sb = srow + (uint32_t)(st) * STG_BYTES;                         \
        _Pragma("unroll")                                                              \
        for (int j = 0; j < 2; j++) {                                                  \
            const int sj = sg + j;                                                     \
            const uint32_t co = (uint32_t)sj * 16;                                     \
            asm volatile("cp.async.cg.shared.global [%0], [%1], 16;" ::                \
                "r"(sb + co), "l"(gA + (ko) + sj*8));                                  \
            asm volatile("cp.async.cg.shared.global [%0], [%1], 16;" ::                \
                "r"(sb + STAGE_H*2 + co), "l"(gB + (ko) + sj*8));                      \
        }                                                                              \
        asm volatile("cp.async.commit_group;" ::: "memory");                           \
    } while (0)

    const int lane = tid & 31;
    const int wm = (tid >> 7);
    const int wn = (tid >> 5) & 3;
    const int grp = lane >> 2, qid = lane & 3;
    const int mb = wm * 64, nb = wn * 32;

    // ldmatrix address components
    const int a_row = (lane & 15);
    const int a_k8  = (lane >> 4) << 3;
    const int b_row = ((lane >> 4) << 3) + (lane & 7);
    const int b_k8  = ((lane >> 3) & 1) << 3;

    float acc[4][4][4];
    #pragma unroll
    for (int i = 0; i < 4; i++)
        #pragma unroll
        for (int j = 0; j < 4; j++)
            #pragma unroll
            for (int q = 0; q < 4; q++) acc[i][j][q] = 0.f;

    const int KT = K >> 5;
    LOADSTAGE(0, 0);
    LOADSTAGE(1, 32);
    LOADSTAGE(2, 64);

    for (int kt = 0; kt < KT; kt++) {
        const int st = kt & (NSTAGE - 1);
        asm volatile("cp.async.wait_group 2;" ::: "memory");
        __syncthreads();
        if (kt + 3 < KT) LOADSTAGE((kt + 3) & (NSTAGE - 1), (kt + 3) * 32);
        else             asm volatile("cp.async.commit_group;" ::: "memory");

        const uint32_t sA = sbase + (uint32_t)st * STG_BYTES;
        const uint32_t sB = sA + STAGE_H * 2;

        #pragma unroll
        for (int ks = 0; ks < 32; ks += 16) {
            uint32_t ar[4][4], br[4][2];
            #pragma unroll
            for (int mt = 0; mt < 4; mt++) {
                const uint32_t addr = sA +
                    (uint32_t)(((mb + mt*16 + a_row) * LDT + ks + a_k8) << 1);
                ldsm4(ar[mt][0], ar[mt][1], ar[mt][2], ar[mt][3], addr);
            }
            #pragma unroll
            for (int ntp = 0; ntp < 4; ntp += 2) {
                const uint32_t addr = sB +
                    (uint32_t)(((nb + ntp*8 + b_row) * LDT + ks + b_k8) << 1);
                ldsm4(br[ntp][0], br[ntp][1], br[ntp+1][0], br[ntp+1][1], addr);
            }
            #pragma unroll
            for (int mt = 0; mt < 4; mt++)
                #pragma unroll
                for (int nt = 0; nt < 4; nt++) {
                    float* c = acc[mt][nt];
                    asm volatile(
                        "mma.sync.aligned.m16n8k16.row.col.f32.f16.f16.f32 "
                        "{%0,%1,%2,%3}, {%4,%5,%6,%7}, {%8,%9}, {%0,%1,%2,%3};\n"
                        : "+f"(c[0]), "+f"(c[1]), "+f"(c[2]), "+f"(c[3])
                        : "r"(ar[mt][0]), "r"(ar[mt][1]), "r"(ar[mt][2]), "r"(ar[mt][3]),
                          "r"(br[nt][0]), "r"(br[nt][1]));
                }
        }
        // no bottom barrier — ring slot overwritten next iteration was last
        // read in iteration kt-1, ordered by the top barrier.
    }

    // ---------------- epilogue ----------------
    __syncthreads();
    if constexpr (EPI == 5) {
        // reset scan chunk counters for the fused scan kernel (ordered by the
        // kernel boundary between this GEMM and the scan launch)
        if (blockIdx.x == 0 && blockIdx.y == 0 && tid < CH) g_cnt[tid] = 0;
    }
    #pragma unroll
    for (int mt = 0; mt < 4; mt++) {
        const size_t r0 = (size_t)block_row + mb + mt*16 + grp;
        const size_t r1 = r0 + 8;
        #pragma unroll
        for (int nt = 0; nt < 4; nt++) {
            const int col = block_col + nb + nt*8 + 2*qid;
            const float* c = acc[mt][nt];
            if constexpr (EPI == 5) {
                if (blockIdx.x < 8) {            // r -> sigmoid fp16
                    const size_t i0 = r0 * 1024 + col;
                    const size_t i1 = r1 * 1024 + col;
                    *reinterpret_cast<uint32_t*>(&Ch[i0]) = packh(hsig(c[0]), hsig(c[1]));
                    *reinterpret_cast<uint32_t*>(&Ch[i1]) = packh(hsig(c[2]), hsig(c[3]));
                } else if (blockIdx.x < 16) {    // v -> fp16 raw
                    const size_t i0 = r0 * 1024 + (col - 1024);
                    const size_t i1 = r1 * 1024 + (col - 1024);
                    *reinterpret_cast<uint32_t*>(&Cv[i0]) =
                        packh(__float2half(c[0]), __float2half(c[1]));
                    *reinterpret_cast<uint32_t*>(&Cv[i1]) =
                        packh(__float2half(c[2]), __float2half(c[3]));
                } else {                         // (w,k) pair -> e fp16
                    const int d = (col - 2048) >> 1;
                    Ce[r0 * 1024 + d] = __float2half(expf(c[1] - expf(c[0])));
                    Ce[r1 * 1024 + d] = __float2half(expf(c[3] - expf(c[2])));
                }
            } else if constexpr (EPI == 6) {
                if (blockIdx.x < 8) {            // rec -> sigmoid fp32 (r2)
                    const size_t i0 = r0 * 1024 + col;
                    const size_t i1 = r1 * 1024 + col;
                    *reinterpret_cast<float2*>(C + i0) =
                        make_float2(1.f/(1.f+expf(-c[0])), 1.f/(1.f+expf(-c[1])));
                    *reinterpret_cast<float2*>(C + i1) =
                        make_float2(1.f/(1.f+expf(-c[2])), 1.f/(1.f+expf(-c[3])));
                } else {                         // key -> relu^2 fp16 (k2)
                    const size_t i0 = r0 * 4096 + (col - 1024);
                    const size_t i1 = r1 * 4096 + (col - 1024);
                    float t0 = fmaxf(c[0],0.f), t1 = fmaxf(c[1],0.f);
                    float t2 = fmaxf(c[2],0.f), t3 = fmaxf(c[3],0.f);
                    *reinterpret_cast<uint32_t*>(&Ch[i0]) =
                        packh(__float2half(t0*t0), __float2half(t1*t1));
                    *reinterpret_cast<uint32_t*>(&Ch[i1]) =
                        packh(__float2half(t2*t2), __float2half(t3*t3));
                }
            } else {
                const size_t i0 = r0 * (size_t)N + col;
                const size_t i1 = r1 * (size_t)N + col;
                float2 o0, o1;
                if constexpr (EPI == 3) {
                    const float2 rr0 = *reinterpret_cast<const float2*>(R + i0);
                    const float2 rr1 = *reinterpret_cast<const float2*>(R + i1);
                    o0 = make_float2(c[0] + rr0.x, c[1] + rr0.y);
                    o1 = make_float2(c[2] + rr1.x, c[3] + rr1.y);
                } else { // EPI 4: R + MUL*acc
                    const float2 rr0 = *reinterpret_cast<const float2*>(R + i0);
                    const float2 rr1 = *reinterpret_cast<const float2*>(R + i1);
                    const float2 mm0 = *reinterpret_cast<const float2*>(MUL + i0);
                    const float2 mm1 = *reinterpret_cast<const float2*>(MUL + i1);
                    o0 = make_float2(rr0.x + mm0.x*c[0], rr0.y + mm0.y*c[1]);
                    o1 = make_float2(rr1.x + mm1.x*c[2], rr1.y + mm1.y*c[3]);
                }
                *reinterpret_cast<float2*>(C + i0) = o0;
                *reinterpret_cast<float2*>(C + i1) = o1;
            }
        }
    }
    #undef LOADSTAGE
}

// ---------------- fused single-pass WKV scan (decoupled chunk signaling) ------
// Each 256-thread block covers ONE chunk c (all threads share c).
// Producers (low blockIdx / low c) run first per CLC bid ordering; all 512
// blocks are co-resident anyway (no smem, low regs).
__global__ void scan_fused(const __half* __restrict__ r, const __half* __restrict__ e,
                           const __half* __restrict__ v, const float* __restrict__ td,
                           float* __restrict__ loc, __half* __restrict__ rw,
                           float* __restrict__ state, int write_state)
{
    const int idx = blockIdx.x * blockDim.x + threadIdx.x;
    const int c  = idx >> 12;
    const int bd = idx & 4095;
    const int b  = bd >> 10;
    const int d  = bd & 1023;
    const float decay = expf(td[d]);
    const float dl    = expf(td[d] * (float)CL);
    const size_t base = ((size_t)(b * Sq + c * CL)) * 1024 + d;

    // ---- phase 1: local scan (no carries), publish loc ----
    float num = 0.f, den = 0.f;
    #pragma unroll 4
    for (int s = 0; s < CL; s++) {
        const size_t off = base + (size_t)s * 1024;
        const float ev = __half2float(e[off]);
        num = fmaf(decay, num, ev * __half2float(v[off]));
        den = fmaf(decay, den, ev);
    }
    const size_t ci0 = ((size_t)c * Bq + b) * 2 * Dq + d;
    loc[ci0]      = num;
    loc[ci0 + Dq] = den;
    __threadfence();
    __syncthreads();
    if (threadIdx.x == 0) atomicAdd(&g_cnt[c], 1);

    // ---- phase 2: wait for all previous chunks, fold carries ----
    float cn = 0.f, cd = 0.f;
    if (c > 0) {
        if (threadIdx.x == 0) {
            for (int cc = 0; cc < c; cc++) {
                while (atomicAdd(&g_cnt[cc], 0) < BLKS_PER_CHUNK) __nanosleep(64);
            }
        }
        __syncthreads();
        __threadfence();
        for (int cc = 0; cc < c; cc++) {
            const size_t ci = ((size_t)cc * Bq + b) * 2 * Dq + d;
            cn = dl * cn + loc[ci];
            cd = dl * cd + loc[ci + Dq];
        }
    }

    // ---- phase 3: rescan with carries (e/v now L2-hot), emit r*wkv ----
    num = cn; den = cd;
    #pragma unroll 4
    for (int s = 0; s < CL; s++) {
        const size_t off = base + (size_t)s * 1024;
        const float ev = __half2float(e[off]);
        num = fmaf(decay, num, ev * __half2float(v[off]));
        den = fmaf(decay, den, ev);
        rw[off] = __float2half(__half2float(r[off]) * (num / (den + 1e-8f)));
    }
    if (write_state && c == CH - 1) {
        state[(size_t)b*2*Dq + d]      = num;
        state[(size_t)b*2*Dq + Dq + d] = den;
    }
}

// ---------------- launch ----------------
extern "C" void kernel_launch(void* const* d_in, const int* in_sizes, int n_in,
                              void* d_out, int out_size)
{
    (void)in_sizes; (void)n_in;
    const float* x     = (const float*)d_in[0];
    const float* ln1_g = (const float*)d_in[1];
    const float* ln1_b = (const float*)d_in[2];
    const float* ln2_g = (const float*)d_in[3];
    const float* ln2_b = (const float*)d_in[4];
    const float* Wr    = (const float*)d_in[5];
    const float* Ww    = (const float*)d_in[6];
    const float* Wk    = (const float*)d_in[7];
    const float* Wv    = (const float*)d_in[8];
    const float* Wo    = (const float*)d_in[9];
    const float* td    = (const float*)d_in[10];
    const float* Wkey  = (const float*)d_in[12];
    const float* Wval  = (const float*)d_in[13];
    const float* Wrec  = (const float*)d_in[14];

    __half *xn,*wq,*wo,*wrk,*wval,*r16,*v16,*rw,*k2,*eb;
    float *x1,*r2,*loc;
    cudaGetSymbolAddress((void**)&xn, g_xn);
    cudaGetSymbolAddress((void**)&wq, g_wqkvw);  cudaGetSymbolAddress((void**)&wo, g_wo);
    cudaGetSymbolAddress((void**)&wrk, g_wrk);   cudaGetSymbolAddress((void**)&wval, g_wval);
    cudaGetSymbolAddress((void**)&r16, g_r16);   cudaGetSymbolAddress((void**)&v16, g_v16);
    cudaGetSymbolAddress((void**)&eb, g_e);
    cudaGetSymbolAddress((void**)&rw, g_rw);     cudaGetSymbolAddress((void**)&k2, g_k2);
    cudaGetSymbolAddress((void**)&x1, g_x1);
    cudaGetSymbolAddress((void**)&r2, g_r2);     cudaGetSymbolAddress((void**)&loc, g_loc);

    float* xout = (float*)d_out;
    const int write_state = (out_size >= Mq*Dq + Bq*2*Dq) ? 1 : 0;
    float* state = xout + (size_t)Mq*Dq;

    cudaFuncSetAttribute(mma_gemm<3>, cudaFuncAttributeMaxDynamicSharedMemorySize, SMEM_BYTES);
    cudaFuncSetAttribute(mma_gemm<4>, cudaFuncAttributeMaxDynamicSharedMemorySize, SMEM_BYTES);
    cudaFuncSetAttribute(mma_gemm<5>, cudaFuncAttributeMaxDynamicSharedMemorySize, SMEM_BYTES);
    cudaFuncSetAttribute(mma_gemm<6>, cudaFuncAttributeMaxDynamicSharedMemorySize, SMEM_BYTES);

    const int nDD4 = Dq*Dq/4, nFD4 = Fq*Dq/4;
    const int kqD = Dq/4;
    uint2* wq2  = (uint2*)wq;
    uint2* wrk2 = (uint2*)wrk;

    // [1] ln1
    ln_cvt_kernel<<<Mq, 256>>>(x, ln1_g, ln1_b, (uint2*)xn);

    // [2] all weight converts (fp32 -> fp16), Ww/Wk row-interleaved into wq[2048:]
    CvtJobs js;
    js.j[0] = { (const float4*)Wr,   wq2,                      nDD4, kqD,   1 };
    js.j[1] = { (const float4*)Wv,   wq2 + (size_t)1024*kqD,   nDD4, kqD,   1 };
    js.j[2] = { (const float4*)Ww,   wq2 + (size_t)2048*kqD,   nDD4, kqD,   2 };
    js.j[3] = { (const float4*)Wk,   wq2 + (size_t)2049*kqD,   nDD4, kqD,   2 };
    js.j[4] = { (const float4*)Wo,   (uint2*)wo,               nDD4, kqD,   1 };
    js.j[5] = { (const float4*)Wrec, wrk2,                     nDD4, kqD,   1 };
    js.j[6] = { (const float4*)Wkey, wrk2 + (size_t)1024*kqD,  nFD4, kqD,   1 };
    js.j[7] = { (const float4*)Wval, (uint2*)wval,             nFD4, Fq/4,  1 };
    cvtall_kernel<<<dim3(nFD4/256, 8), 256>>>(js);

    // [3] fused r|v|wk GEMM -> r16, v16, e(fp16); also resets g_cnt
    mma_gemm<5><<<dim3(32, 64), 256, SMEM_BYTES>>>(xn, wq,
        nullptr, r16, v16, eb, nullptr, nullptr, 4096, Dq);
    // [4] fused single-pass scan -> rw, state
    scan_fused<<<(CH*Bq*Dq)/256, 256>>>(r16, eb, v16, td, loc, rw, state, write_state);
    // [5] Wo GEMM: x1 = x + (r*wkv)@Wo^T
    mma_gemm<3><<<dim3(8, 64), 256, SMEM_BYTES>>>(rw, wo,
        x1, nullptr, nullptr, nullptr, x, nullptr, 1024, Dq);
    // [6] ln2
    ln_cvt_kernel<<<Mq, 256>>>(x1, ln2_g, ln2_b, (uint2*)xn);
    // [7] fused rec|key GEMM: r2 fp32 [M,1024] + k2 fp16 [M,4096]
    mma_gemm<6><<<dim3(40, 64), 256, SMEM_BYTES>>>(xn, wrk,
        r2, k2, nullptr, nullptr, nullptr, nullptr, 5120, Dq);
    // [8] Wval GEMM: out = x1 + r2*(k2@Wval^T)
    mma_gemm<4><<<dim3(8, 64), 256, SMEM_BYTES>>>(k2, wval,
        xout, nullptr, nullptr, nullptr, x1, r2, 1024, Fq);
}

// round 16
// speedup vs baseline: 1.0134x; 1.0134x over previous
#include <cuda_runtime.h>
#include <cuda_fp16.h>
#include <cstdint>
#include <math.h>

#define Bq 4
#define Sq 2048
#define Dq 1024
#define Fq 4096
#define Mq (Bq*Sq)     // 8192
#define CH 32
#define CL (Sq/CH)     // 64
#define LDT 40         // smem row stride in halves (BK=32 + 8 pad)
#define STAGE_H (128*LDT)            // halves per tile (5120)
#define TILES_PER_STAGE 2            // A, B
#define STG_BYTES (TILES_PER_STAGE*STAGE_H*2)   // 20480
#define NSTAGE 4
#define SMEM_BYTES (NSTAGE*STG_BYTES)           // 81920

// ---------------- scratch ----------------
__device__ __half g_xn[(size_t)Mq*Dq];
__device__ __half g_wqkvw[(size_t)4*Dq*Dq];   // [r rows | v rows | w/k interleaved]
__device__ __half g_wo[(size_t)Dq*Dq];
__device__ __half g_wrk[(size_t)(Dq+Fq)*Dq];  // [rec|key]
__device__ __half g_wval[(size_t)Dq*Fq];
__device__ __half g_r16[(size_t)Mq*Dq];
__device__ __half g_v16[(size_t)Mq*Dq];
__device__ __half g_e  [(size_t)Mq*Dq];       // exp(k - exp(w)), fp16
__device__ float  g_x1 [(size_t)Mq*Dq];
__device__ float  g_r2 [(size_t)Mq*Dq];
__device__ __half g_rw[(size_t)Mq*Dq];
__device__ __half g_k2[(size_t)Mq*Fq];
__device__ float  g_loc[(size_t)CH*Bq*2*Dq];

// ---------------- helpers ----------------
__device__ __forceinline__ uint32_t packh(__half a, __half b) {
    __half2 p(a, b);
    return *reinterpret_cast<uint32_t*>(&p);
}
__device__ __forceinline__ uint2 cvt4(float4 v) {
    return make_uint2(packh(__float2half(v.x), __float2half(v.y)),
                      packh(__float2half(v.z), __float2half(v.w)));
}
__device__ __forceinline__ __half hsig(float x) {
    return __float2half(1.f / (1.f + expf(-x)));
}
__device__ __forceinline__ void ldsm4(uint32_t& r0, uint32_t& r1, uint32_t& r2, uint32_t& r3,
                                      uint32_t addr) {
    asm volatile("ldmatrix.sync.aligned.m8n8.x4.shared.b16 {%0,%1,%2,%3}, [%4];"
                 : "=r"(r0), "=r"(r1), "=r"(r2), "=r"(r3) : "r"(addr));
}

// ---------------- fused weight convert (with optional row interleave) ----------
struct CvtJob  { const float4* s; uint2* d; int n4; int kq; int rstride; };
struct CvtJobs { CvtJob j[8]; };
__global__ void cvtall_kernel(CvtJobs js)
{
    const CvtJob jb = js.j[blockIdx.y];
    const int i = blockIdx.x * blockDim.x + threadIdx.x;
    if (i >= jb.n4) return;
    const int row = i / jb.kq;
    const int col = i - row * jb.kq;
    jb.d[(size_t)row * jb.rstride * jb.kq + col] = cvt4(jb.s[i]);
}

// ---------------- layernorm -> fp16 ----------------
__global__ void ln_cvt_kernel(const float* __restrict__ x,
                              const float* __restrict__ gamma,
                              const float* __restrict__ beta,
                              uint2* __restrict__ oh)
{
    const int row = blockIdx.x;
    const float4* xr = reinterpret_cast<const float4*>(x) + (size_t)row * (Dq/4);
    float4 v = xr[threadIdx.x];
    float s  = v.x + v.y + v.z + v.w;
    float ss = v.x*v.x + v.y*v.y + v.z*v.z + v.w*v.w;
    #pragma unroll
    for (int o = 16; o > 0; o >>= 1) {
        s  += __shfl_xor_sync(0xffffffffu, s,  o);
        ss += __shfl_xor_sync(0xffffffffu, ss, o);
    }
    __shared__ float rs[8], rss[8];
    const int warp = threadIdx.x >> 5;
    if ((threadIdx.x & 31) == 0) { rs[warp] = s; rss[warp] = ss; }
    __syncthreads();
    float ts = 0.f, tss = 0.f;
    #pragma unroll
    for (int i = 0; i < 8; i++) { ts += rs[i]; tss += rss[i]; }
    const float mu   = ts * (1.0f/Dq);
    const float var  = tss * (1.0f/Dq) - mu*mu;
    const float rstd = rsqrtf(var + 1e-5f);
    const float4 g4 = reinterpret_cast<const float4*>(gamma)[threadIdx.x];
    const float4 b4 = reinterpret_cast<const float4*>(beta )[threadIdx.x];
    float4 o;
    o.x = (v.x - mu)*rstd*g4.x + b4.x;
    o.y = (v.y - mu)*rstd*g4.y + b4.y;
    o.z = (v.z - mu)*rstd*g4.z + b4.z;
    o.w = (v.w - mu)*rstd*g4.w + b4.w;
    oh[(size_t)row * (Dq/4) + threadIdx.x] = cvt4(o);
}

// ---------------- HMMA GEMM: BK=32, 4-stage ring, wait_group 2 ----------------
// ONE __syncthreads per kt. ldmatrix fragment loads. (R11/R14 mainloop.)
// EPI: 3 = acc + R -> C;  4 = R + MUL(float)*acc -> C
//      5 = qkvw: x<8 sigmoid->Ch fp16; 8<=x<16 raw->Cv fp16; x>=16 (w,k) pairs ->
//          Ce = expf(k - expf(w)) fp16 at col (col-2048)/2
//      6 = rec|key: x<8 sigmoid->C fp32 [M,1024]; else relu^2 -> Ch fp16 [M,4096]
template<int EPI>
__global__ void __launch_bounds__(256, 2)
mma_gemm(const __half* __restrict__ A, const __half* __restrict__ B,
         float* __restrict__ C, __half* __restrict__ Ch,
         __half* __restrict__ Cv, __half* __restrict__ Ce,
         const float* __restrict__ R, const float* __restrict__ MUL,
         int N, int K)
{
    extern __shared__ __half dyn[];

    const int tid = threadIdx.x;
    const int block_row = blockIdx.y * 128;
    const int block_col = blockIdx.x * 128;

    const uint32_t sbase = (uint32_t)__cvta_generic_to_shared(dyn);

    // loaders: 2 threads per row, each 2 x 16B per tile
    const int lr = tid >> 1;
    const int sg = (tid & 1) * 2;
    const __half* gA = A + (size_t)(block_row + lr) * K;
    const __half* gB = B + (size_t)(block_col + lr) * K;
    const uint32_t srow = sbase + (uint32_t)(lr * LDT) * 2;

    #define LOADSTAGE(st, ko)                                                          \
    do {                                                                               \
        const uint32_t sb = srow + (uint32_t)(st) * STG_BYTES;                         \
        _Pragma("unroll")                                                              \
        for (int j = 0; j < 2; j++) {                                                  \
            const int sj = sg + j;                                                     \
            const uint32_t co = (uint32_t)sj * 16;                                     \
            asm volatile("cp.async.cg.shared.global [%0], [%1], 16;" ::                \
                "r"(sb + co), "l"(gA + (ko) + sj*8));                                  \
            asm volatile("cp.async.cg.shared.global [%0], [%1], 16;" ::                \
                "r"(sb + STAGE_H*2 + co), "l"(gB + (ko) + sj*8));                      \
        }                                                                              \
        asm volatile("cp.async.commit_group;" ::: "memory");                           \
    } while (0)

    const int lane = tid & 31;
    const int wm = (tid >> 7);
    const int wn = (tid >> 5) & 3;
    const int grp = lane >> 2, qid = lane & 3;
    const int mb = wm * 64, nb = wn * 32;

    // ldmatrix address components
    const int a_row = (lane & 15);
    const int a_k8  = (lane >> 4) << 3;
    const int b_row = ((lane >> 4) << 3) + (lane & 7);
    const int b_k8  = ((lane >> 3) & 1) << 3;

    float acc[4][4][4];
    #pragma unroll
    for (int i = 0; i < 4; i++)
        #pragma unroll
        for (int j = 0; j < 4; j++)
            #pragma unroll
            for (int q = 0; q < 4; q++) acc[i][j][q] = 0.f;

    const int KT = K >> 5;
    LOADSTAGE(0, 0);
    LOADSTAGE(1, 32);
    LOADSTAGE(2, 64);

    for (int kt = 0; kt < KT; kt++) {
        const int st = kt & (NSTAGE - 1);
        asm volatile("cp.async.wait_group 2;" ::: "memory");
        __syncthreads();
        if (kt + 3 < KT) LOADSTAGE((kt + 3) & (NSTAGE - 1), (kt + 3) * 32);
        else             asm volatile("cp.async.commit_group;" ::: "memory");

        const uint32_t sA = sbase + (uint32_t)st * STG_BYTES;
        const uint32_t sB = sA + STAGE_H * 2;

        #pragma unroll
        for (int ks = 0; ks < 32; ks += 16) {
            uint32_t ar[4][4], br[4][2];
            #pragma unroll
            for (int mt = 0; mt < 4; mt++) {
                const uint32_t addr = sA +
                    (uint32_t)(((mb + mt*16 + a_row) * LDT + ks + a_k8) << 1);
                ldsm4(ar[mt][0], ar[mt][1], ar[mt][2], ar[mt][3], addr);
            }
            #pragma unroll
            for (int ntp = 0; ntp < 4; ntp += 2) {
                const uint32_t addr = sB +
                    (uint32_t)(((nb + ntp*8 + b_row) * LDT + ks + b_k8) << 1);
                ldsm4(br[ntp][0], br[ntp][1], br[ntp+1][0], br[ntp+1][1], addr);
            }
            #pragma unroll
            for (int mt = 0; mt < 4; mt++)
                #pragma unroll
                for (int nt = 0; nt < 4; nt++) {
                    float* c = acc[mt][nt];
                    asm volatile(
                        "mma.sync.aligned.m16n8k16.row.col.f32.f16.f16.f32 "
                        "{%0,%1,%2,%3}, {%4,%5,%6,%7}, {%8,%9}, {%0,%1,%2,%3};\n"
                        : "+f"(c[0]), "+f"(c[1]), "+f"(c[2]), "+f"(c[3])
                        : "r"(ar[mt][0]), "r"(ar[mt][1]), "r"(ar[mt][2]), "r"(ar[mt][3]),
                          "r"(br[nt][0]), "r"(br[nt][1]));
                }
        }
        // no bottom barrier — ring slot overwritten next iteration was last
        // read in iteration kt-1, ordered by the top barrier.
    }

    // ---------------- epilogue ----------------
    __syncthreads();
    #pragma unroll
    for (int mt = 0; mt < 4; mt++) {
        const size_t r0 = (size_t)block_row + mb + mt*16 + grp;
        const size_t r1 = r0 + 8;
        #pragma unroll
        for (int nt = 0; nt < 4; nt++) {
            const int col = block_col + nb + nt*8 + 2*qid;
            const float* c = acc[mt][nt];
            if constexpr (EPI == 5) {
                if (blockIdx.x < 8) {            // r -> sigmoid fp16
                    const size_t i0 = r0 * 1024 + col;
                    const size_t i1 = r1 * 1024 + col;
                    *reinterpret_cast<uint32_t*>(&Ch[i0]) = packh(hsig(c[0]), hsig(c[1]));
                    *reinterpret_cast<uint32_t*>(&Ch[i1]) = packh(hsig(c[2]), hsig(c[3]));
                } else if (blockIdx.x < 16) {    // v -> fp16 raw
                    const size_t i0 = r0 * 1024 + (col - 1024);
                    const size_t i1 = r1 * 1024 + (col - 1024);
                    *reinterpret_cast<uint32_t*>(&Cv[i0]) =
                        packh(__float2half(c[0]), __float2half(c[1]));
                    *reinterpret_cast<uint32_t*>(&Cv[i1]) =
                        packh(__float2half(c[2]), __float2half(c[3]));
                } else {                         // (w,k) pair -> e fp16
                    const int d = (col - 2048) >> 1;
                    Ce[r0 * 1024 + d] = __float2half(expf(c[1] - expf(c[0])));
                    Ce[r1 * 1024 + d] = __float2half(expf(c[3] - expf(c[2])));
                }
            } else if constexpr (EPI == 6) {
                if (blockIdx.x < 8) {            // rec -> sigmoid fp32 (r2)
                    const size_t i0 = r0 * 1024 + col;
                    const size_t i1 = r1 * 1024 + col;
                    *reinterpret_cast<float2*>(C + i0) =
                        make_float2(1.f/(1.f+expf(-c[0])), 1.f/(1.f+expf(-c[1])));
                    *reinterpret_cast<float2*>(C + i1) =
                        make_float2(1.f/(1.f+expf(-c[2])), 1.f/(1.f+expf(-c[3])));
                } else {                         // key -> relu^2 fp16 (k2)
                    const size_t i0 = r0 * 4096 + (col - 1024);
                    const size_t i1 = r1 * 4096 + (col - 1024);
                    float t0 = fmaxf(c[0],0.f), t1 = fmaxf(c[1],0.f);
                    float t2 = fmaxf(c[2],0.f), t3 = fmaxf(c[3],0.f);
                    *reinterpret_cast<uint32_t*>(&Ch[i0]) =
                        packh(__float2half(t0*t0), __float2half(t1*t1));
                    *reinterpret_cast<uint32_t*>(&Ch[i1]) =
                        packh(__float2half(t2*t2), __float2half(t3*t3));
                }
            } else {
                const size_t i0 = r0 * (size_t)N + col;
                const size_t i1 = r1 * (size_t)N + col;
                float2 o0, o1;
                if constexpr (EPI == 3) {
                    const float2 rr0 = *reinterpret_cast<const float2*>(R + i0);
                    const float2 rr1 = *reinterpret_cast<const float2*>(R + i1);
                    o0 = make_float2(c[0] + rr0.x, c[1] + rr0.y);
                    o1 = make_float2(c[2] + rr1.x, c[3] + rr1.y);
                } else { // EPI 4: R + MUL*acc
                    const float2 rr0 = *reinterpret_cast<const float2*>(R + i0);
                    const float2 rr1 = *reinterpret_cast<const float2*>(R + i1);
                    const float2 mm0 = *reinterpret_cast<const float2*>(MUL + i0);
                    const float2 mm1 = *reinterpret_cast<const float2*>(MUL + i1);
                    o0 = make_float2(rr0.x + mm0.x*c[0], rr0.y + mm0.y*c[1]);
                    o1 = make_float2(rr1.x + mm1.x*c[2], rr1.y + mm1.y*c[3]);
                }
                *reinterpret_cast<float2*>(C + i0) = o0;
                *reinterpret_cast<float2*>(C + i1) = o1;
            }
        }
    }
    #undef LOADSTAGE
}

// ---------------- chunked WKV scan, 2 channels per thread (half2/float2) ------
__global__ void scan_p1(const __half* __restrict__ e, const __half* __restrict__ v,
                        const float* __restrict__ td, float* __restrict__ loc)
{
    const int idx = blockIdx.x * blockDim.x + threadIdx.x;   // CH*Bq*512
    const int c   = idx >> 11;
    const int bd2 = idx & 2047;
    const int b   = bd2 >> 9;
    const int d   = (bd2 & 511) << 1;                        // even channel
    const float2 dec = make_float2(expf(td[d]), expf(td[d+1]));
    float2 num = make_float2(0.f, 0.f), den = make_float2(0.f, 0.f);
    const size_t base = ((size_t)(b * Sq + c * CL)) * 1024 + d;
    #pragma unroll 4
    for (int s = 0; s < CL; s++) {
        const size_t off = base + (size_t)s * 1024;
        const float2 ev = __half22float2(*reinterpret_cast<const __half2*>(e + off));
        const float2 vv = __half22float2(*reinterpret_cast<const __half2*>(v + off));
        num.x = fmaf(dec.x, num.x, ev.x * vv.x);
        num.y = fmaf(dec.y, num.y, ev.y * vv.y);
        den.x = fmaf(dec.x, den.x, ev.x);
        den.y = fmaf(dec.y, den.y, ev.y);
    }
    const size_t ci = ((size_t)c * Bq + b) * 2 * Dq + d;
    *reinterpret_cast<float2*>(loc + ci)      = num;
    *reinterpret_cast<float2*>(loc + ci + Dq) = den;
}

__global__ void scan_p3(const __half* __restrict__ r, const __half* __restrict__ e,
                        const __half* __restrict__ v, const float* __restrict__ td,
                        const float* __restrict__ loc, __half* __restrict__ rw,
                        float* __restrict__ state, int write_state)
{
    const int idx = blockIdx.x * blockDim.x + threadIdx.x;
    const int c   = idx >> 11;
    const int bd2 = idx & 2047;
    const int b   = bd2 >> 9;
    const int d   = (bd2 & 511) << 1;
    const float2 dec = make_float2(expf(td[d]), expf(td[d+1]));
    const float2 dl  = make_float2(expf(td[d] * (float)CL), expf(td[d+1] * (float)CL));
    float2 num = make_float2(0.f, 0.f), den = make_float2(0.f, 0.f);
    for (int cc = 0; cc < c; cc++) {
        const size_t ci = ((size_t)cc * Bq + b) * 2 * Dq + d;
        const float2 ln = *reinterpret_cast<const float2*>(loc + ci);
        const float2 ld = *reinterpret_cast<const float2*>(loc + ci + Dq);
        num.x = fmaf(dl.x, num.x, ln.x); num.y = fmaf(dl.y, num.y, ln.y);
        den.x = fmaf(dl.x, den.x, ld.x); den.y = fmaf(dl.y, den.y, ld.y);
    }
    const size_t base = ((size_t)(b * Sq + c * CL)) * 1024 + d;
    #pragma unroll 4
    for (int s = 0; s < CL; s++) {
        const size_t off = base + (size_t)s * 1024;
        const float2 ev = __half22float2(*reinterpret_cast<const __half2*>(e + off));
        const float2 vv = __half22float2(*reinterpret_cast<const __half2*>(v + off));
        const float2 rv = __half22float2(*reinterpret_cast<const __half2*>(r + off));
        num.x = fmaf(dec.x, num.x, ev.x * vv.x);
        num.y = fmaf(dec.y, num.y, ev.y * vv.y);
        den.x = fmaf(dec.x, den.x, ev.x);
        den.y = fmaf(dec.y, den.y, ev.y);
        const float w0 = rv.x * (num.x / (den.x + 1e-8f));
        const float w1 = rv.y * (num.y / (den.y + 1e-8f));
        *reinterpret_cast<uint32_t*>(rw + off) = packh(__float2half(w0), __float2half(w1));
    }
    if (write_state && c == CH - 1) {
        *reinterpret_cast<float2*>(state + (size_t)b*2*Dq + d)      = num;
        *reinterpret_cast<float2*>(state + (size_t)b*2*Dq + Dq + d) = den;
    }
}

// ---------------- launch ----------------
extern "C" void kernel_launch(void* const* d_in, const int* in_sizes, int n_in,
                              void* d_out, int out_size)
{
    (void)in_sizes; (void)n_in;
    const float* x     = (const float*)d_in[0];
    const float* ln1_g = (const float*)d_in[1];
    const float* ln1_b = (const float*)d_in[2];
    const float* ln2_g = (const float*)d_in[3];
    const float* ln2_b = (const float*)d_in[4];
    const float* Wr    = (const float*)d_in[5];
    const float* Ww    = (const float*)d_in[6];
    const float* Wk    = (const float*)d_in[7];
    const float* Wv    = (const float*)d_in[8];
    const float* Wo    = (const float*)d_in[9];
    const float* td    = (const float*)d_in[10];
    const float* Wkey  = (const float*)d_in[12];
    const float* Wval  = (const float*)d_in[13];
    const float* Wrec  = (const float*)d_in[14];

    __half *xn,*wq,*wo,*wrk,*wval,*r16,*v16,*rw,*k2,*eb;
    float *x1,*r2,*loc;
    cudaGetSymbolAddress((void**)&xn, g_xn);
    cudaGetSymbolAddress((void**)&wq, g_wqkvw);  cudaGetSymbolAddress((void**)&wo, g_wo);
    cudaGetSymbolAddress((void**)&wrk, g_wrk);   cudaGetSymbolAddress((void**)&wval, g_wval);
    cudaGetSymbolAddress((void**)&r16, g_r16);   cudaGetSymbolAddress((void**)&v16, g_v16);
    cudaGetSymbolAddress((void**)&eb, g_e);
    cudaGetSymbolAddress((void**)&rw, g_rw);     cudaGetSymbolAddress((void**)&k2, g_k2);
    cudaGetSymbolAddress((void**)&x1, g_x1);
    cudaGetSymbolAddress((void**)&r2, g_r2);     cudaGetSymbolAddress((void**)&loc, g_loc);

    float* xout = (float*)d_out;
    const int write_state = (out_size >= Mq*Dq + Bq*2*Dq) ? 1 : 0;
    float* state = xout + (size_t)Mq*Dq;

    cudaFuncSetAttribute(mma_gemm<3>, cudaFuncAttributeMaxDynamicSharedMemorySize, SMEM_BYTES);
    cudaFuncSetAttribute(mma_gemm<4>, cudaFuncAttributeMaxDynamicSharedMemorySize, SMEM_BYTES);
    cudaFuncSetAttribute(mma_gemm<5>, cudaFuncAttributeMaxDynamicSharedMemorySize, SMEM_BYTES);
    cudaFuncSetAttribute(mma_gemm<6>, cudaFuncAttributeMaxDynamicSharedMemorySize, SMEM_BYTES);

    const int nDD4 = Dq*Dq/4, nFD4 = Fq*Dq/4;
    const int kqD = Dq/4;
    uint2* wq2  = (uint2*)wq;
    uint2* wrk2 = (uint2*)wrk;

    // [1] ln1
    ln_cvt_kernel<<<Mq, 256>>>(x, ln1_g, ln1_b, (uint2*)xn);

    // [2] all weight converts (fp32 -> fp16), Ww/Wk row-interleaved into wq[2048:]
    CvtJobs js;
    js.j[0] = { (const float4*)Wr,   wq2,                      nDD4, kqD,   1 };
    js.j[1] = { (const float4*)Wv,   wq2 + (size_t)1024*kqD,   nDD4, kqD,   1 };
    js.j[2] = { (const float4*)Ww,   wq2 + (size_t)2048*kqD,   nDD4, kqD,   2 };
    js.j[3] = { (const float4*)Wk,   wq2 + (size_t)2049*kqD,   nDD4, kqD,   2 };
    js.j[4] = { (const float4*)Wo,   (uint2*)wo,               nDD4, kqD,   1 };
    js.j[5] = { (const float4*)Wrec, wrk2,                     nDD4, kqD,   1 };
    js.j[6] = { (const float4*)Wkey, wrk2 + (size_t)1024*kqD,  nFD4, kqD,   1 };
    js.j[7] = { (const float4*)Wval, (uint2*)wval,             nFD4, Fq/4,  1 };
    cvtall_kernel<<<dim3(nFD4/256, 8), 256>>>(js);

    // [3] fused r|v|wk GEMM -> r16, v16, e(fp16)
    mma_gemm<5><<<dim3(32, 64), 256, SMEM_BYTES>>>(xn, wq,
        nullptr, r16, v16, eb, nullptr, nullptr, 4096, Dq);
    // [4][5] scan (2 channels per thread)
    scan_p1<<<(CH*Bq*Dq/2)/256, 256>>>(eb, v16, td, loc);
    scan_p3<<<(CH*Bq*Dq/2)/256, 256>>>(r16, eb, v16, td, loc, rw, state, write_state);
    // [6] Wo GEMM: x1 = x + (r*wkv)@Wo^T
    mma_gemm<3><<<dim3(8, 64), 256, SMEM_BYTES>>>(rw, wo,
        x1, nullptr, nullptr, nullptr, x, nullptr, 1024, Dq);
    // [7] ln2
    ln_cvt_kernel<<<Mq, 256>>>(x1, ln2_g, ln2_b, (uint2*)xn);
    // [8] fused rec|key GEMM: r2 fp32 [M,1024] + k2 fp16 [M,4096]
    mma_gemm<6><<<dim3(40, 64), 256, SMEM_BYTES>>>(xn, wrk,
        r2, k2, nullptr, nullptr, nullptr, nullptr, 5120, Dq);
    // [9] Wval GEMM: out = x1 + r2*(k2@Wval^T)
    mma_gemm<4><<<dim3(8, 64), 256, SMEM_BYTES>>>(k2, wval,
        xout, nullptr, nullptr, nullptr, x1, r2, 1024, Fq);
}

// round 17
// speedup vs baseline: 1.0195x; 1.0060x over previous
#include <cuda_runtime.h>
#include <cuda_fp16.h>
#include <cstdint>
#include <math.h>

#define Bq 4
#define Sq 2048
#define Dq 1024
#define Fq 4096
#define Mq (Bq*Sq)     // 8192
#define CH 32
#define CL (Sq/CH)     // 64
#define LDT 40         // smem row stride in halves (BK=32 + 8 pad)
#define STAGE_H (128*LDT)            // halves per tile (5120)
#define TILES_PER_STAGE 2            // A, B
#define STG_BYTES (TILES_PER_STAGE*STAGE_H*2)   // 20480
#define NSTAGE 4
#define SMEM_BYTES (NSTAGE*STG_BYTES)           // 81920

// ---------------- scratch ----------------
__device__ __half g_xn[(size_t)Mq*Dq];
__device__ __half g_wqkvw[(size_t)4*Dq*Dq];   // [r rows | v rows | w/k interleaved]
__device__ __half g_wo[(size_t)Dq*Dq];
__device__ __half g_wrk[(size_t)(Dq+Fq)*Dq];  // [rec|key]
__device__ __half g_wval[(size_t)Dq*Fq];
__device__ __half g_r16[(size_t)Mq*Dq];
__device__ __half g_v16[(size_t)Mq*Dq];
__device__ __half g_e  [(size_t)Mq*Dq];       // exp(k - exp(w)), fp16
__device__ float  g_x1 [(size_t)Mq*Dq];
__device__ float  g_r2 [(size_t)Mq*Dq];
__device__ __half g_rw[(size_t)Mq*Dq];
__device__ __half g_k2[(size_t)Mq*Fq];
__device__ float  g_loc[(size_t)CH*Bq*2*Dq];

// ---------------- helpers ----------------
__device__ __forceinline__ uint32_t packh(__half a, __half b) {
    __half2 p(a, b);
    return *reinterpret_cast<uint32_t*>(&p);
}
__device__ __forceinline__ uint2 cvt4(float4 v) {
    return make_uint2(packh(__float2half(v.x), __float2half(v.y)),
                      packh(__float2half(v.z), __float2half(v.w)));
}
__device__ __forceinline__ __half hsig(float x) {
    return __float2half(1.f / (1.f + expf(-x)));
}
__device__ __forceinline__ void ldsm4(uint32_t& r0, uint32_t& r1, uint32_t& r2, uint32_t& r3,
                                      uint32_t addr) {
    asm volatile("ldmatrix.sync.aligned.m8n8.x4.shared.b16 {%0,%1,%2,%3}, [%4];"
                 : "=r"(r0), "=r"(r1), "=r"(r2), "=r"(r3) : "r"(addr));
}

// ---------------- fused weight convert (with optional row interleave) ----------
struct CvtJob  { const float4* s; uint2* d; int n4; int kq; int rstride; };
struct CvtJobs { CvtJob j[8]; };
__global__ void cvtall_kernel(CvtJobs js)
{
    const CvtJob jb = js.j[blockIdx.y];
    const int i = blockIdx.x * blockDim.x + threadIdx.x;
    if (i >= jb.n4) return;
    const int row = i / jb.kq;
    const int col = i - row * jb.kq;
    jb.d[(size_t)row * jb.rstride * jb.kq + col] = cvt4(jb.s[i]);
}

// ---------------- layernorm -> fp16 ----------------
__global__ void ln_cvt_kernel(const float* __restrict__ x,
                              const float* __restrict__ gamma,
                              const float* __restrict__ beta,
                              uint2* __restrict__ oh)
{
    const int row = blockIdx.x;
    const float4* xr = reinterpret_cast<const float4*>(x) + (size_t)row * (Dq/4);
    float4 v = xr[threadIdx.x];
    float s  = v.x + v.y + v.z + v.w;
    float ss = v.x*v.x + v.y*v.y + v.z*v.z + v.w*v.w;
    #pragma unroll
    for (int o = 16; o > 0; o >>= 1) {
        s  += __shfl_xor_sync(0xffffffffu, s,  o);
        ss += __shfl_xor_sync(0xffffffffu, ss, o);
    }
    __shared__ float rs[8], rss[8];
    const int warp = threadIdx.x >> 5;
    if ((threadIdx.x & 31) == 0) { rs[warp] = s; rss[warp] = ss; }
    __syncthreads();
    float ts = 0.f, tss = 0.f;
    #pragma unroll
    for (int i = 0; i < 8; i++) { ts += rs[i]; tss += rss[i]; }
    const float mu   = ts * (1.0f/Dq);
    const float var  = tss * (1.0f/Dq) - mu*mu;
    const float rstd = rsqrtf(var + 1e-5f);
    const float4 g4 = reinterpret_cast<const float4*>(gamma)[threadIdx.x];
    const float4 b4 = reinterpret_cast<const float4*>(beta )[threadIdx.x];
    float4 o;
    o.x = (v.x - mu)*rstd*g4.x + b4.x;
    o.y = (v.y - mu)*rstd*g4.y + b4.y;
    o.z = (v.z - mu)*rstd*g4.z + b4.z;
    o.w = (v.w - mu)*rstd*g4.w + b4.w;
    oh[(size_t)row * (Dq/4) + threadIdx.x] = cvt4(o);
}

// ---------------- HMMA GEMM: BK=32, 4-stage ring, wait_group 2 ----------------
// ONE __syncthreads per kt. ldmatrix fragment loads. (R11/R14 mainloop.)
// EPI: 3 = acc + R -> C;  4 = R + MUL(float)*acc -> C
//      5 = qkvw: x<8 sigmoid->Ch fp16; 8<=x<16 raw->Cv fp16; x>=16 (w,k) pairs ->
//          Ce = expf(k - expf(w)) fp16 at col (col-2048)/2
//      6 = rec|key: x<8 sigmoid->C fp32 [M,1024]; else relu^2 -> Ch fp16 [M,4096]
template<int EPI>
__global__ void __launch_bounds__(256, 2)
mma_gemm(const __half* __restrict__ A, const __half* __restrict__ B,
         float* __restrict__ C, __half* __restrict__ Ch,
         __half* __restrict__ Cv, __half* __restrict__ Ce,
         const float* __restrict__ R, const float* __restrict__ MUL,
         int N, int K)
{
    extern __shared__ __half dyn[];

    const int tid = threadIdx.x;
    const int block_row = blockIdx.y * 128;
    const int block_col = blockIdx.x * 128;

    const uint32_t sbase = (uint32_t)__cvta_generic_to_shared(dyn);

    // loaders: 2 threads per row, each 2 x 16B per tile
    const int lr = tid >> 1;
    const int sg = (tid & 1) * 2;
    const __half* gA = A + (size_t)(block_row + lr) * K;
    const __half* gB = B + (size_t)(block_col + lr) * K;
    const uint32_t srow = sbase + (uint32_t)(lr * LDT) * 2;

    #define LOADSTAGE(st, ko)                                                          \
    do {                                                                               \
        const uint32_t sb = srow + (uint32_t)(st) * STG_BYTES;                         \
        _Pragma("unroll")                                                              \
        for (int j = 0; j < 2; j++) {                                                  \
            const int sj = sg + j;                                                     \
            const uint32_t co = (uint32_t)sj * 16;                                     \
            asm volatile("cp.async.cg.shared.global [%0], [%1], 16;" ::                \
                "r"(sb + co), "l"(gA + (ko) + sj*8));                                  \
            asm volatile("cp.async.cg.shared.global [%0], [%1], 16;" ::                \
                "r"(sb + STAGE_H*2 + co), "l"(gB + (ko) + sj*8));                      \
        }                                                                              \
        asm volatile("cp.async.commit_group;" ::: "memory");                           \
    } while (0)

    const int lane = tid & 31;
    const int wm = (tid >> 7);
    const int wn = (tid >> 5) & 3;
    const int grp = lane >> 2, qid = lane & 3;
    const int mb = wm * 64, nb = wn * 32;

    // ldmatrix address components
    const int a_row = (lane & 15);
    const int a_k8  = (lane >> 4) << 3;
    const int b_row = ((lane >> 4) << 3) + (lane & 7);
    const int b_k8  = ((lane >> 3) & 1) << 3;

    float acc[4][4][4];
    #pragma unroll
    for (int i = 0; i < 4; i++)
        #pragma unroll
        for (int j = 0; j < 4; j++)
            #pragma unroll
            for (int q = 0; q < 4; q++) acc[i][j][q] = 0.f;

    const int KT = K >> 5;
    LOADSTAGE(0, 0);
    LOADSTAGE(1, 32);
    LOADSTAGE(2, 64);

    for (int kt = 0; kt < KT; kt++) {
        const int st = kt & (NSTAGE - 1);
        asm volatile("cp.async.wait_group 2;" ::: "memory");
        __syncthreads();
        if (kt + 3 < KT) LOADSTAGE((kt + 3) & (NSTAGE - 1), (kt + 3) * 32);
        else             asm volatile("cp.async.commit_group;" ::: "memory");

        const uint32_t sA = sbase + (uint32_t)st * STG_BYTES;
        const uint32_t sB = sA + STAGE_H * 2;

        #pragma unroll
        for (int ks = 0; ks < 32; ks += 16) {
            uint32_t ar[4][4], br[4][2];
            #pragma unroll
            for (int mt = 0; mt < 4; mt++) {
                const uint32_t addr = sA +
                    (uint32_t)(((mb + mt*16 + a_row) * LDT + ks + a_k8) << 1);
                ldsm4(ar[mt][0], ar[mt][1], ar[mt][2], ar[mt][3], addr);
            }
            #pragma unroll
            for (int ntp = 0; ntp < 4; ntp += 2) {
                const uint32_t addr = sB +
                    (uint32_t)(((nb + ntp*8 + b_row) * LDT + ks + b_k8) << 1);
                ldsm4(br[ntp][0], br[ntp][1], br[ntp+1][0], br[ntp+1][1], addr);
            }
            #pragma unroll
            for (int mt = 0; mt < 4; mt++)
                #pragma unroll
                for (int nt = 0; nt < 4; nt++) {
                    float* c = acc[mt][nt];
                    asm volatile(
                        "mma.sync.aligned.m16n8k16.row.col.f32.f16.f16.f32 "
                        "{%0,%1,%2,%3}, {%4,%5,%6,%7}, {%8,%9}, {%0,%1,%2,%3};\n"
                        : "+f"(c[0]), "+f"(c[1]), "+f"(c[2]), "+f"(c[3])
                        : "r"(ar[mt][0]), "r"(ar[mt][1]), "r"(ar[mt][2]), "r"(ar[mt][3]),
                          "r"(br[nt][0]), "r"(br[nt][1]));
                }
        }
        // no bottom barrier — ring slot overwritten next iteration was last
        // read in iteration kt-1, ordered by the top barrier.
    }

    // ---------------- epilogue ----------------
    __syncthreads();
    #pragma unroll
    for (int mt = 0; mt < 4; mt++) {
        const size_t r0 = (size_t)block_row + mb + mt*16 + grp;
        const size_t r1 = r0 + 8;
        #pragma unroll
        for (int nt = 0; nt < 4; nt++) {
            const int col = block_col + nb + nt*8 + 2*qid;
            const float* c = acc[mt][nt];
            if constexpr (EPI == 5) {
                if (blockIdx.x < 8) {            // r -> sigmoid fp16
                    const size_t i0 = r0 * 1024 + col;
                    const size_t i1 = r1 * 1024 + col;
                    *reinterpret_cast<uint32_t*>(&Ch[i0]) = packh(hsig(c[0]), hsig(c[1]));
                    *reinterpret_cast<uint32_t*>(&Ch[i1]) = packh(hsig(c[2]), hsig(c[3]));
                } else if (blockIdx.x < 16) {    // v -> fp16 raw
                    const size_t i0 = r0 * 1024 + (col - 1024);
                    const size_t i1 = r1 * 1024 + (col - 1024);
                    *reinterpret_cast<uint32_t*>(&Cv[i0]) =
                        packh(__float2half(c[0]), __float2half(c[1]));
                    *reinterpret_cast<uint32_t*>(&Cv[i1]) =
                        packh(__float2half(c[2]), __float2half(c[3]));
                } else {                         // (w,k) pair -> e fp16
                    const int d = (col - 2048) >> 1;
                    Ce[r0 * 1024 + d] = __float2half(expf(c[1] - expf(c[0])));
                    Ce[r1 * 1024 + d] = __float2half(expf(c[3] - expf(c[2])));
                }
            } else if constexpr (EPI == 6) {
                if (blockIdx.x < 8) {            // rec -> sigmoid fp32 (r2)
                    const size_t i0 = r0 * 1024 + col;
                    const size_t i1 = r1 * 1024 + col;
                    *reinterpret_cast<float2*>(C + i0) =
                        make_float2(1.f/(1.f+expf(-c[0])), 1.f/(1.f+expf(-c[1])));
                    *reinterpret_cast<float2*>(C + i1) =
                        make_float2(1.f/(1.f+expf(-c[2])), 1.f/(1.f+expf(-c[3])));
                } else {                         // key -> relu^2 fp16 (k2)
                    const size_t i0 = r0 * 4096 + (col - 1024);
                    const size_t i1 = r1 * 4096 + (col - 1024);
                    float t0 = fmaxf(c[0],0.f), t1 = fmaxf(c[1],0.f);
                    float t2 = fmaxf(c[2],0.f), t3 = fmaxf(c[3],0.f);
                    *reinterpret_cast<uint32_t*>(&Ch[i0]) =
                        packh(__float2half(t0*t0), __float2half(t1*t1));
                    *reinterpret_cast<uint32_t*>(&Ch[i1]) =
                        packh(__float2half(t2*t2), __float2half(t3*t3));
                }
            } else {
                const size_t i0 = r0 * (size_t)N + col;
                const size_t i1 = r1 * (size_t)N + col;
                float2 o0, o1;
                if constexpr (EPI == 3) {
                    const float2 rr0 = *reinterpret_cast<const float2*>(R + i0);
                    const float2 rr1 = *reinterpret_cast<const float2*>(R + i1);
                    o0 = make_float2(c[0] + rr0.x, c[1] + rr0.y);
                    o1 = make_float2(c[2] + rr1.x, c[3] + rr1.y);
                } else { // EPI 4: R + MUL*acc
                    const float2 rr0 = *reinterpret_cast<const float2*>(R + i0);
                    const float2 rr1 = *reinterpret_cast<const float2*>(R + i1);
                    const float2 mm0 = *reinterpret_cast<const float2*>(MUL + i0);
                    const float2 mm1 = *reinterpret_cast<const float2*>(MUL + i1);
                    o0 = make_float2(rr0.x + mm0.x*c[0], rr0.y + mm0.y*c[1]);
                    o1 = make_float2(rr1.x + mm1.x*c[2], rr1.y + mm1.y*c[3]);
                }
                *reinterpret_cast<float2*>(C + i0) = o0;
                *reinterpret_cast<float2*>(C + i1) = o1;
            }
        }
    }
    #undef LOADSTAGE
}

// ---------------- chunked WKV scan (R14 scalar form, deeper unroll) -----------
__global__ void scan_p1(const __half* __restrict__ e, const __half* __restrict__ v,
                        const float* __restrict__ td, float* __restrict__ loc)
{
    const int idx = blockIdx.x * blockDim.x + threadIdx.x;
    const int c  = idx >> 12;
    const int bd = idx & 4095;
    const int b  = bd >> 10;
    const int d  = bd & 1023;
    const float decay = expf(td[d]);
    float num = 0.f, den = 0.f;
    const size_t base = ((size_t)(b * Sq + c * CL)) * 1024 + d;
    #pragma unroll 8
    for (int s = 0; s < CL; s++) {
        const size_t off = base + (size_t)s * 1024;
        const float ev = __half2float(e[off]);
        num = fmaf(decay, num, ev * __half2float(v[off]));
        den = fmaf(decay, den, ev);
    }
    const size_t ci = ((size_t)c * Bq + b) * 2 * Dq + d;
    loc[ci]      = num;
    loc[ci + Dq] = den;
}

__global__ void scan_p3(const __half* __restrict__ r, const __half* __restrict__ e,
                        const __half* __restrict__ v, const float* __restrict__ td,
                        const float* __restrict__ loc, __half* __restrict__ rw,
                        float* __restrict__ state, int write_state)
{
    const int idx = blockIdx.x * blockDim.x + threadIdx.x;
    const int c  = idx >> 12;
    const int bd = idx & 4095;
    const int b  = bd >> 10;
    const int d  = bd & 1023;
    const float decay = expf(td[d]);
    const float dl    = expf(td[d] * (float)CL);
    float num = 0.f, den = 0.f;
    for (int cc = 0; cc < c; cc++) {
        const size_t ci = ((size_t)cc * Bq + b) * 2 * Dq + d;
        num = dl * num + loc[ci];
        den = dl * den + loc[ci + Dq];
    }
    const size_t base = ((size_t)(b * Sq + c * CL)) * 1024 + d;
    #pragma unroll 8
    for (int s = 0; s < CL; s++) {
        const size_t off = base + (size_t)s * 1024;
        const float ev = __half2float(e[off]);
        num = fmaf(decay, num, ev * __half2float(v[off]));
        den = fmaf(decay, den, ev);
        rw[off] = __float2half(__half2float(r[off]) * (num / (den + 1e-8f)));
    }
    if (write_state && c == CH - 1) {
        state[(size_t)b*2*Dq + d]      = num;
        state[(size_t)b*2*Dq + Dq + d] = den;
    }
}

// ---------------- launch ----------------
extern "C" void kernel_launch(void* const* d_in, const int* in_sizes, int n_in,
                              void* d_out, int out_size)
{
    (void)in_sizes; (void)n_in;
    const float* x     = (const float*)d_in[0];
    const float* ln1_g = (const float*)d_in[1];
    const float* ln1_b = (const float*)d_in[2];
    const float* ln2_g = (const float*)d_in[3];
    const float* ln2_b = (const float*)d_in[4];
    const float* Wr    = (const float*)d_in[5];
    const float* Ww    = (const float*)d_in[6];
    const float* Wk    = (const float*)d_in[7];
    const float* Wv    = (const float*)d_in[8];
    const float* Wo    = (const float*)d_in[9];
    const float* td    = (const float*)d_in[10];
    const float* Wkey  = (const float*)d_in[12];
    const float* Wval  = (const float*)d_in[13];
    const float* Wrec  = (const float*)d_in[14];

    __half *xn,*wq,*wo,*wrk,*wval,*r16,*v16,*rw,*k2,*eb;
    float *x1,*r2,*loc;
    cudaGetSymbolAddress((void**)&xn, g_xn);
    cudaGetSymbolAddress((void**)&wq, g_wqkvw);  cudaGetSymbolAddress((void**)&wo, g_wo);
    cudaGetSymbolAddress((void**)&wrk, g_wrk);   cudaGetSymbolAddress((void**)&wval, g_wval);
    cudaGetSymbolAddress((void**)&r16, g_r16);   cudaGetSymbolAddress((void**)&v16, g_v16);
    cudaGetSymbolAddress((void**)&eb, g_e);
    cudaGetSymbolAddress((void**)&rw, g_rw);     cudaGetSymbolAddress((void**)&k2, g_k2);
    cudaGetSymbolAddress((void**)&x1, g_x1);
    cudaGetSymbolAddress((void**)&r2, g_r2);     cudaGetSymbolAddress((void**)&loc, g_loc);

    float* xout = (float*)d_out;
    const int write_state = (out_size >= Mq*Dq + Bq*2*Dq) ? 1 : 0;
    float* state = xout + (size_t)Mq*Dq;

    cudaFuncSetAttribute(mma_gemm<3>, cudaFuncAttributeMaxDynamicSharedMemorySize, SMEM_BYTES);
    cudaFuncSetAttribute(mma_gemm<4>, cudaFuncAttributeMaxDynamicSharedMemorySize, SMEM_BYTES);
    cudaFuncSetAttribute(mma_gemm<5>, cudaFuncAttributeMaxDynamicSharedMemorySize, SMEM_BYTES);
    cudaFuncSetAttribute(mma_gemm<6>, cudaFuncAttributeMaxDynamicSharedMemorySize, SMEM_BYTES);

    const int nDD4 = Dq*Dq/4, nFD4 = Fq*Dq/4;
    const int kqD = Dq/4;
    uint2* wq2  = (uint2*)wq;
    uint2* wrk2 = (uint2*)wrk;

    // [1] ln1
    ln_cvt_kernel<<<Mq, 256>>>(x, ln1_g, ln1_b, (uint2*)xn);

    // [2] all weight converts (fp32 -> fp16), Ww/Wk row-interleaved into wq[2048:]
    CvtJobs js;
    js.j[0] = { (const float4*)Wr,   wq2,                      nDD4, kqD,   1 };
    js.j[1] = { (const float4*)Wv,   wq2 + (size_t)1024*kqD,   nDD4, kqD,   1 };
    js.j[2] = { (const float4*)Ww,   wq2 + (size_t)2048*kqD,   nDD4, kqD,   2 };
    js.j[3] = { (const float4*)Wk,   wq2 + (size_t)2049*kqD,   nDD4, kqD,   2 };
    js.j[4] = { (const float4*)Wo,   (uint2*)wo,               nDD4, kqD,   1 };
    js.j[5] = { (const float4*)Wrec, wrk2,                     nDD4, kqD,   1 };
    js.j[6] = { (const float4*)Wkey, wrk2 + (size_t)1024*kqD,  nFD4, kqD,   1 };
    js.j[7] = { (const float4*)Wval, (uint2*)wval,             nFD4, Fq/4,  1 };
    cvtall_kernel<<<dim3(nFD4/256, 8), 256>>>(js);

    // [3] fused r|v|wk GEMM -> r16, v16, e(fp16)
    mma_gemm<5><<<dim3(32, 64), 256, SMEM_BYTES>>>(xn, wq,
        nullptr, r16, v16, eb, nullptr, nullptr, 4096, Dq);
    // [4][5] scan
    scan_p1<<<(CH*Bq*Dq)/256, 256>>>(eb, v16, td, loc);
    scan_p3<<<(CH*Bq*Dq)/256, 256>>>(r16, eb, v16, td, loc, rw, state, write_state);
    // [6] Wo GEMM: x1 = x + (r*wkv)@Wo^T
    mma_gemm<3><<<dim3(8, 64), 256, SMEM_BYTES>>>(rw, wo,
        x1, nullptr, nullptr, nullptr, x, nullptr, 1024, Dq);
    // [7] ln2
    ln_cvt_kernel<<<Mq, 256>>>(x1, ln2_g, ln2_b, (uint2*)xn);
    // [8] fused rec|key GEMM: r2 fp32 [M,1024] + k2 fp16 [M,4096]
    mma_gemm<6><<<dim3(40, 64), 256, SMEM_BYTES>>>(xn, wrk,
        r2, k2, nullptr, nullptr, nullptr, nullptr, 5120, Dq);
    // [9] Wval GEMM: out = x1 + r2*(k2@Wval^T)
    mma_gemm<4><<<dim3(8, 64), 256, SMEM_BYTES>>>(k2, wval,
        xout, nullptr, nullptr, nullptr, x1, r2, 1024, Fq);
}